// round 1
// baseline (speedup 1.0000x reference)
#include <cuda_runtime.h>
#include <math.h>

// ---------------- problem constants ----------------
#define LSEQ   2048
#define DMODEL 1024
#define DINNER 2048
#define DSTATE 16
#define DTRANK 64
#define XDBL   96      // dt_rank + 2*d_state
#define NEXP   8
#define HIDDEN 4096
#define NPAIR  4096    // L * top-k

// ---------------- scratch (static device, no allocs) ----------------
__device__ float g_xn   [LSEQ * DMODEL];
__device__ float g_xr   [LSEQ * 2 * DINNER];
__device__ float g_u    [LSEQ * DINNER];
__device__ float g_xdbl [LSEQ * XDBL];
__device__ float g_delta[LSEQ * DINNER];
__device__ float g_y    [LSEQ * DINNER];
__device__ float g_xm2  [LSEQ * DMODEL];
__device__ float g_xm2n [LSEQ * DMODEL];
__device__ int   g_top_e[LSEQ * 2];
__device__ float g_top_v[LSEQ * 2];
__device__ int   g_cnt[NEXP];
__device__ int   g_cur[NEXP];
__device__ int   g_off[NEXP + 1];
__device__ int   g_ptok[NPAIR];
__device__ float g_pw  [NPAIR];
__device__ int   g_tok_pair[LSEQ * 2];
__device__ float g_h [(size_t)NPAIR * HIDDEN];   // 64 MB
__device__ float g_y2[(size_t)NPAIR * DMODEL];   // 16 MB

// ---------------- rmsnorm (row = 1024) ----------------
__global__ void rmsnorm_kernel(const float* __restrict__ x, float* __restrict__ o)
{
    int row = blockIdx.x;
    const float* xp = x + (size_t)row * DMODEL;
    float s = 0.f;
    for (int k = threadIdx.x; k < DMODEL; k += 256) { float v = xp[k]; s += v * v; }
    __shared__ float sh[8];
    #pragma unroll
    for (int off = 16; off; off >>= 1) s += __shfl_xor_sync(0xffffffffu, s, off);
    if ((threadIdx.x & 31) == 0) sh[threadIdx.x >> 5] = s;
    __syncthreads();
    if (threadIdx.x < 8) {
        float v = sh[threadIdx.x];
        #pragma unroll
        for (int off = 4; off; off >>= 1) v += __shfl_xor_sync(0xffu, v, off);
        if (threadIdx.x == 0) sh[0] = v;
    }
    __syncthreads();
    float scale = 32.0f / fmaxf(sqrtf(sh[0]), 1e-12f);   // sqrt(1024)=32
    float* op = o + (size_t)row * DMODEL;
    for (int k = threadIdx.x; k < DMODEL; k += 256) op[k] = xp[k] * scale;
}

// ---------------- generic GEMM: C = epi(A @ W^T) ----------------
// A: (M,K) with row stride lda; W: (N,K) row-major contiguous.
// EPI 0: store. EPI 1: softplus(acc + bias[n]). EPI 2: acc + addsrc[m,n].
template<int EPI>
__global__ void __launch_bounds__(256) gemm_tn(
    const float* __restrict__ A, int lda,
    const float* __restrict__ W,
    float* __restrict__ C, int ldc,
    int M, int N, int K,
    const float* __restrict__ bias,
    const float* __restrict__ addsrc, int ldadd)
{
    __shared__ float As[16][68];
    __shared__ float Bs[16][68];
    int tid = threadIdx.x;
    int m0 = blockIdx.x * 64, n0 = blockIdx.y * 64;
    int tx = tid & 15, ty = tid >> 4;
    int lr = tid >> 2;
    int lk = (tid & 3) << 2;
    int am = m0 + lr;
    int wn = n0 + lr;
    bool a_ok = am < M;
    bool w_ok = wn < N;
    const float* Arow = A + (size_t)(a_ok ? am : 0) * lda;
    const float* Wrow = W + (size_t)(w_ok ? wn : 0) * K;
    float acc[4][4] = {};
    for (int k0 = 0; k0 < K; k0 += 16) {
        float4 av = a_ok ? *(const float4*)(Arow + k0 + lk) : make_float4(0, 0, 0, 0);
        float4 wv = w_ok ? *(const float4*)(Wrow + k0 + lk) : make_float4(0, 0, 0, 0);
        __syncthreads();
        As[lk][lr] = av.x; As[lk + 1][lr] = av.y; As[lk + 2][lr] = av.z; As[lk + 3][lr] = av.w;
        Bs[lk][lr] = wv.x; Bs[lk + 1][lr] = wv.y; Bs[lk + 2][lr] = wv.z; Bs[lk + 3][lr] = wv.w;
        __syncthreads();
        #pragma unroll
        for (int k = 0; k < 16; k++) {
            float a[4], b[4];
            #pragma unroll
            for (int i = 0; i < 4; i++) a[i] = As[k][ty * 4 + i];
            #pragma unroll
            for (int j = 0; j < 4; j++) b[j] = Bs[k][tx * 4 + j];
            #pragma unroll
            for (int i = 0; i < 4; i++)
                #pragma unroll
                for (int j = 0; j < 4; j++)
                    acc[i][j] += a[i] * b[j];
        }
    }
    #pragma unroll
    for (int i = 0; i < 4; i++) {
        int m = m0 + ty * 4 + i;
        if (m >= M) continue;
        #pragma unroll
        for (int j = 0; j < 4; j++) {
            int n = n0 + tx * 4 + j;
            if (n >= N) continue;
            float v = acc[i][j];
            if (EPI == 1) { float z = v + bias[n]; v = (z > 20.f) ? z : log1pf(__expf(z)); }
            else if (EPI == 2) { v += addsrc[(size_t)m * ldadd + n]; }
            C[(size_t)m * ldc + n] = v;
        }
    }
}

// ---------------- causal depthwise conv(4) + silu ----------------
__global__ void conv_silu(const float* __restrict__ xr, const float* __restrict__ cw,
                          const float* __restrict__ cb, float* __restrict__ u)
{
    int idx = blockIdx.x * 256 + threadIdx.x;     // over L*DINNER
    int t = idx >> 11, d = idx & (DINNER - 1);
    float w0 = cw[d * 4], w1 = cw[d * 4 + 1], w2 = cw[d * 4 + 2], w3 = cw[d * 4 + 3];
    float s = cb[d];
    const float* col = xr + d;
    if (t >= 3) s += col[(size_t)(t - 3) * (2 * DINNER)] * w0;
    if (t >= 2) s += col[(size_t)(t - 2) * (2 * DINNER)] * w1;
    if (t >= 1) s += col[(size_t)(t - 1) * (2 * DINNER)] * w2;
    s += col[(size_t)t * (2 * DINNER)] * w3;
    u[idx] = s / (1.f + __expf(-s));
}

// ---------------- selective scan ----------------
// block = 128 threads = 8 channels x 16 states; grid = DINNER/8
__global__ void scan_kernel(const float* __restrict__ delta,
                            const float* __restrict__ u,
                            const float* __restrict__ xdbl,
                            const float* __restrict__ A_log,
                            const float* __restrict__ Dvec,
                            const float* __restrict__ xr,
                            float* __restrict__ y)
{
    int lane16 = threadIdx.x & 15;
    int ch = threadIdx.x >> 4;             // 0..7
    int d = blockIdx.x * 8 + ch;
    float A = -__expf(A_log[d * DSTATE + lane16]);
    float Dd = Dvec[d];
    float h = 0.f;
    __shared__ float sB[32][16], sC[32][16], sdl[32][8], su[32][8], sre[32][8];
    for (int t0 = 0; t0 < LSEQ; t0 += 32) {
        __syncthreads();
        for (int i = threadIdx.x; i < 512; i += 128) {
            int tt = i >> 4, n = i & 15;
            const float* xb = xdbl + (size_t)(t0 + tt) * XDBL;
            sB[tt][n] = xb[DTRANK + n];
            sC[tt][n] = xb[DTRANK + DSTATE + n];
        }
        for (int i = threadIdx.x; i < 256; i += 128) {
            int tt = i >> 3, c = i & 7;
            int dd = blockIdx.x * 8 + c;
            size_t off = (size_t)(t0 + tt) * DINNER + dd;
            sdl[tt][c] = delta[off];
            su[tt][c]  = u[off];
            sre[tt][c] = xr[(size_t)(t0 + tt) * (2 * DINNER) + DINNER + dd];
        }
        __syncthreads();
        for (int tt = 0; tt < 32; tt++) {
            float dl = sdl[tt][ch];
            float uu = su[tt][ch];
            float dA = __expf(dl * A);
            h = dA * h + dl * sB[tt][lane16] * uu;
            float p = h * sC[tt][lane16];
            #pragma unroll
            for (int o = 8; o; o >>= 1) p += __shfl_xor_sync(0xffffffffu, p, o, 16);
            if (lane16 == 0) {
                float yv = p + uu * Dd;
                float r = sre[tt][ch];
                yv *= r / (1.f + __expf(-r));
                y[(size_t)(t0 + tt) * DINNER + d] = yv;
            }
        }
    }
}

// ---------------- gating: GEMV + softmax + top-2 ----------------
__global__ void gate_topk(const float* __restrict__ X, const float* __restrict__ gw,
                          int* __restrict__ te, float* __restrict__ tv)
{
    __shared__ float sg[NEXP * DMODEL];    // 32 KB
    for (int i = threadIdx.x; i < NEXP * DMODEL; i += 128) sg[i] = gw[i];
    __syncthreads();
    int warp = threadIdx.x >> 5, lane = threadIdx.x & 31;
    int t = blockIdx.x * 4 + warp;
    const float* xp = X + (size_t)t * DMODEL;
    float acc[NEXP] = {};
    for (int k = lane; k < DMODEL; k += 32) {
        float xv = xp[k];
        #pragma unroll
        for (int e = 0; e < NEXP; e++) acc[e] += xv * sg[e * DMODEL + k];
    }
    #pragma unroll
    for (int e = 0; e < NEXP; e++)
        #pragma unroll
        for (int o = 16; o; o >>= 1) acc[e] += __shfl_xor_sync(0xffffffffu, acc[e], o);
    if (lane == 0) {
        float m = acc[0];
        #pragma unroll
        for (int e = 1; e < NEXP; e++) m = fmaxf(m, acc[e]);
        float g[NEXP];
        #pragma unroll
        for (int e = 0; e < NEXP; e++) g[e] = __expf(acc[e] - m);
        int i0 = 0;
        #pragma unroll
        for (int e = 1; e < NEXP; e++) if (g[e] > g[i0]) i0 = e;
        int i1 = (i0 == 0) ? 1 : 0;
        #pragma unroll
        for (int e = 0; e < NEXP; e++) if (e != i0 && g[e] > g[i1]) i1 = e;
        float inv = 1.f / (g[i0] + g[i1]);
        te[t * 2] = i0; te[t * 2 + 1] = i1;
        tv[t * 2] = g[i0] * inv; tv[t * 2 + 1] = g[i1] * inv;
    }
}

// ---------------- routing ----------------
__global__ void route_zero(int* cnt, int* cur)
{
    if (threadIdx.x < NEXP) { cnt[threadIdx.x] = 0; cur[threadIdx.x] = 0; }
}
__global__ void route_count(const int* __restrict__ te, int* cnt)
{
    int t = blockIdx.x * 256 + threadIdx.x;
    atomicAdd(&cnt[te[t * 2]], 1);
    atomicAdd(&cnt[te[t * 2 + 1]], 1);
}
__global__ void route_offsets(const int* __restrict__ cnt, int* off)
{
    int s = 0;
    for (int e = 0; e < NEXP; e++) { off[e] = s; s += cnt[e]; }
    off[NEXP] = s;
}
__global__ void route_scatter(const int* __restrict__ te, const float* __restrict__ tv,
                              const int* __restrict__ off, int* cur,
                              int* ptok, float* pw, int* tok_pair)
{
    int t = blockIdx.x * 256 + threadIdx.x;
    #pragma unroll
    for (int k = 0; k < 2; k++) {
        int e = te[t * 2 + k];
        int pos = atomicAdd(&cur[e], 1);
        int p = off[e] + pos;
        ptok[p] = t;
        pw[p] = tv[t * 2 + k];
        tok_pair[t * 2 + k] = p;
    }
}

// ---------------- MoE GEMM 1: H[p] = gelu(X[tok[p]] @ w1[e]^T) ----------------
__global__ void __launch_bounds__(256) moe_gemm1(
    const float* __restrict__ X, const float* __restrict__ w1, float* __restrict__ H,
    const int* __restrict__ off, const int* __restrict__ ptok)
{
    int e = blockIdx.z;
    int base = off[e];
    int rows = off[e + 1] - base;
    int m0 = blockIdx.x * 64;
    if (m0 >= rows) return;
    const float* W = w1 + (size_t)e * HIDDEN * DMODEL;
    __shared__ float As[16][68];
    __shared__ float Bs[16][68];
    int tid = threadIdx.x;
    int n0 = blockIdx.y * 64;
    int tx = tid & 15, ty = tid >> 4;
    int lr = tid >> 2;
    int lk = (tid & 3) << 2;
    int mr = m0 + lr;
    bool a_ok = mr < rows;
    int tok = a_ok ? ptok[base + mr] : 0;
    const float* Arow = X + (size_t)tok * DMODEL;
    const float* Wrow = W + (size_t)(n0 + lr) * DMODEL;
    float acc[4][4] = {};
    for (int k0 = 0; k0 < DMODEL; k0 += 16) {
        float4 av = a_ok ? *(const float4*)(Arow + k0 + lk) : make_float4(0, 0, 0, 0);
        float4 wv = *(const float4*)(Wrow + k0 + lk);
        __syncthreads();
        As[lk][lr] = av.x; As[lk + 1][lr] = av.y; As[lk + 2][lr] = av.z; As[lk + 3][lr] = av.w;
        Bs[lk][lr] = wv.x; Bs[lk + 1][lr] = wv.y; Bs[lk + 2][lr] = wv.z; Bs[lk + 3][lr] = wv.w;
        __syncthreads();
        #pragma unroll
        for (int k = 0; k < 16; k++) {
            float a[4], b[4];
            #pragma unroll
            for (int i = 0; i < 4; i++) a[i] = As[k][ty * 4 + i];
            #pragma unroll
            for (int j = 0; j < 4; j++) b[j] = Bs[k][tx * 4 + j];
            #pragma unroll
            for (int i = 0; i < 4; i++)
                #pragma unroll
                for (int j = 0; j < 4; j++)
                    acc[i][j] += a[i] * b[j];
        }
    }
    #pragma unroll
    for (int i = 0; i < 4; i++) {
        int mrow = m0 + ty * 4 + i;
        if (mrow >= rows) continue;
        size_t p = (size_t)(base + mrow);
        #pragma unroll
        for (int j = 0; j < 4; j++) {
            int n = n0 + tx * 4 + j;
            float v = acc[i][j];
            v = 0.5f * v * (1.0f + erff(v * 0.70710678118654752f));   // exact gelu
            H[p * HIDDEN + n] = v;
        }
    }
}

// ---------------- MoE GEMM 2: Y2[p] = H[p] @ w2[e]^T ----------------
__global__ void __launch_bounds__(256) moe_gemm2(
    const float* __restrict__ H, const float* __restrict__ w2, float* __restrict__ Y2,
    const int* __restrict__ off)
{
    int e = blockIdx.z;
    int base = off[e];
    int rows = off[e + 1] - base;
    int m0 = blockIdx.x * 64;
    if (m0 >= rows) return;
    const float* W = w2 + (size_t)e * DMODEL * HIDDEN;
    __shared__ float As[16][68];
    __shared__ float Bs[16][68];
    int tid = threadIdx.x;
    int n0 = blockIdx.y * 64;
    int tx = tid & 15, ty = tid >> 4;
    int lr = tid >> 2;
    int lk = (tid & 3) << 2;
    int mr = m0 + lr;
    bool a_ok = mr < rows;
    const float* Arow = H + (size_t)(base + (a_ok ? mr : 0)) * HIDDEN;
    const float* Wrow = W + (size_t)(n0 + lr) * HIDDEN;
    float acc[4][4] = {};
    for (int k0 = 0; k0 < HIDDEN; k0 += 16) {
        float4 av = a_ok ? *(const float4*)(Arow + k0 + lk) : make_float4(0, 0, 0, 0);
        float4 wv = *(const float4*)(Wrow + k0 + lk);
        __syncthreads();
        As[lk][lr] = av.x; As[lk + 1][lr] = av.y; As[lk + 2][lr] = av.z; As[lk + 3][lr] = av.w;
        Bs[lk][lr] = wv.x; Bs[lk + 1][lr] = wv.y; Bs[lk + 2][lr] = wv.z; Bs[lk + 3][lr] = wv.w;
        __syncthreads();
        #pragma unroll
        for (int k = 0; k < 16; k++) {
            float a[4], b[4];
            #pragma unroll
            for (int i = 0; i < 4; i++) a[i] = As[k][ty * 4 + i];
            #pragma unroll
            for (int j = 0; j < 4; j++) b[j] = Bs[k][tx * 4 + j];
            #pragma unroll
            for (int i = 0; i < 4; i++)
                #pragma unroll
                for (int j = 0; j < 4; j++)
                    acc[i][j] += a[i] * b[j];
        }
    }
    #pragma unroll
    for (int i = 0; i < 4; i++) {
        int mrow = m0 + ty * 4 + i;
        if (mrow >= rows) continue;
        size_t p = (size_t)(base + mrow);
        #pragma unroll
        for (int j = 0; j < 4; j++) {
            int n = n0 + tx * 4 + j;
            Y2[p * DMODEL + n] = acc[i][j];
        }
    }
}

// ---------------- final combine: out = skip + v0*Y2[p0] + v1*Y2[p1] ----------------
__global__ void moe_combine(const float* __restrict__ x, const float* __restrict__ y2,
                            const int* __restrict__ tok_pair, const float* __restrict__ pw,
                            float* __restrict__ out)
{
    int i = blockIdx.x * 256 + threadIdx.x;     // over L*DMODEL
    int t = i >> 10, n = i & (DMODEL - 1);
    int p0 = tok_pair[t * 2], p1 = tok_pair[t * 2 + 1];
    out[i] = x[i] + pw[p0] * y2[(size_t)p0 * DMODEL + n]
                  + pw[p1] * y2[(size_t)p1 * DMODEL + n];
}

// ---------------- launch ----------------
extern "C" void kernel_launch(void* const* d_in, const int* in_sizes, int n_in,
                              void* d_out, int out_size)
{
    (void)in_sizes; (void)n_in; (void)out_size;
    const float* x          = (const float*)d_in[0];
    const float* in_proj_w  = (const float*)d_in[1];
    const float* conv_w     = (const float*)d_in[2];
    const float* conv_b     = (const float*)d_in[3];
    const float* x_proj_w   = (const float*)d_in[4];
    const float* dt_proj_w  = (const float*)d_in[5];
    const float* dt_proj_b  = (const float*)d_in[6];
    const float* A_log      = (const float*)d_in[7];
    const float* Dvec       = (const float*)d_in[8];
    const float* out_proj_w = (const float*)d_in[9];
    const float* gate_w     = (const float*)d_in[10];
    const float* w1         = (const float*)d_in[11];
    const float* w2         = (const float*)d_in[12];
    float* out = (float*)d_out;

    float *p_xn, *p_xr, *p_u, *p_xdbl, *p_delta, *p_y, *p_xm2, *p_xm2n, *p_tv, *p_pw, *p_h, *p_y2;
    int *p_te, *p_cnt, *p_cur, *p_off, *p_ptok, *p_tp;
    cudaGetSymbolAddress((void**)&p_xn, g_xn);
    cudaGetSymbolAddress((void**)&p_xr, g_xr);
    cudaGetSymbolAddress((void**)&p_u, g_u);
    cudaGetSymbolAddress((void**)&p_xdbl, g_xdbl);
    cudaGetSymbolAddress((void**)&p_delta, g_delta);
    cudaGetSymbolAddress((void**)&p_y, g_y);
    cudaGetSymbolAddress((void**)&p_xm2, g_xm2);
    cudaGetSymbolAddress((void**)&p_xm2n, g_xm2n);
    cudaGetSymbolAddress((void**)&p_te, g_top_e);
    cudaGetSymbolAddress((void**)&p_tv, g_top_v);
    cudaGetSymbolAddress((void**)&p_cnt, g_cnt);
    cudaGetSymbolAddress((void**)&p_cur, g_cur);
    cudaGetSymbolAddress((void**)&p_off, g_off);
    cudaGetSymbolAddress((void**)&p_ptok, g_ptok);
    cudaGetSymbolAddress((void**)&p_pw, g_pw);
    cudaGetSymbolAddress((void**)&p_tp, g_tok_pair);
    cudaGetSymbolAddress((void**)&p_h, g_h);
    cudaGetSymbolAddress((void**)&p_y2, g_y2);

    // 1. xn = rmsnorm(x)
    rmsnorm_kernel<<<LSEQ, 256>>>(x, p_xn);
    // 2. xr = xn @ in_proj_w^T   (2048 x 4096, K=1024)
    gemm_tn<0><<<dim3(32, 64), 256>>>(p_xn, DMODEL, in_proj_w, p_xr, 2 * DINNER,
                                      LSEQ, 2 * DINNER, DMODEL, nullptr, nullptr, 0);
    // 3. u = silu(causal_conv(xm) + b)
    conv_silu<<<(LSEQ * DINNER) / 256, 256>>>(p_xr, conv_w, conv_b, p_u);
    // 4. x_dbl = u @ x_proj_w^T  (2048 x 96, K=2048)
    gemm_tn<0><<<dim3(32, 2), 256>>>(p_u, DINNER, x_proj_w, p_xdbl, XDBL,
                                     LSEQ, XDBL, DINNER, nullptr, nullptr, 0);
    // 5. delta = softplus(dt @ dt_proj_w^T + b)  (2048 x 2048, K=64)
    gemm_tn<1><<<dim3(32, 32), 256>>>(p_xdbl, XDBL, dt_proj_w, p_delta, DINNER,
                                      LSEQ, DINNER, DTRANK, dt_proj_b, nullptr, 0);
    // 6. selective scan (+ u*D, * silu(res))
    scan_kernel<<<DINNER / 8, 128>>>(p_delta, p_u, p_xdbl, A_log, Dvec, p_xr, p_y);
    // 7. xm2 = y @ out_proj_w^T + xn  (2048 x 1024, K=2048)
    gemm_tn<2><<<dim3(32, 16), 256>>>(p_y, DINNER, out_proj_w, p_xm2, DMODEL,
                                      LSEQ, DMODEL, DINNER, nullptr, p_xn, DMODEL);
    // 8. xm2n = rmsnorm(xm2)
    rmsnorm_kernel<<<LSEQ, 256>>>(p_xm2, p_xm2n);
    // 9. gating + top-2
    gate_topk<<<LSEQ / 4, 128>>>(p_xm2n, gate_w, p_te, p_tv);
    // 10. routing
    route_zero<<<1, 32>>>(p_cnt, p_cur);
    route_count<<<LSEQ / 256, 256>>>(p_te, p_cnt);
    route_offsets<<<1, 1>>>(p_cnt, p_off);
    route_scatter<<<LSEQ / 256, 256>>>(p_te, p_tv, p_off, p_cur, p_ptok, p_pw, p_tp);
    // 11. expert GEMMs (grouped by expert), then deterministic combine
    moe_gemm1<<<dim3(32, HIDDEN / 64, NEXP), 256>>>(p_xm2n, w1, p_h, p_off, p_ptok);
    moe_gemm2<<<dim3(32, DMODEL / 64, NEXP), 256>>>(p_h, w2, p_y2, p_off);
    moe_combine<<<(LSEQ * DMODEL) / 256, 256>>>(x, p_y2, p_tp, p_pw, out);
}

// round 2
// speedup vs baseline: 1.5186x; 1.5186x over previous
#include <cuda_runtime.h>
#include <math.h>
#include <stdint.h>

// ---------------- problem constants ----------------
#define LSEQ   2048
#define DMODEL 1024
#define DINNER 2048
#define DSTATE 16
#define DTRANK 64
#define XDBL   96      // dt_rank + 2*d_state
#define NEXP   8
#define HIDDEN 4096
#define NPAIR  4096    // L * top-k

// ---------------- scratch (static device, no allocs) ----------------
__device__ float g_xn   [LSEQ * DMODEL];
__device__ float g_xr   [LSEQ * 2 * DINNER];
__device__ float g_u    [LSEQ * DINNER];
__device__ float g_xdbl [LSEQ * XDBL];
__device__ float g_xp   [4 * LSEQ * XDBL];
__device__ float g_delta[LSEQ * DINNER];
__device__ float g_y    [LSEQ * DINNER];
__device__ float g_xm2  [LSEQ * DMODEL];
__device__ float g_xm2n [LSEQ * DMODEL];
__device__ int   g_top_e[LSEQ * 2];
__device__ float g_top_v[LSEQ * 2];
__device__ int   g_cnt[NEXP];
__device__ int   g_cur[NEXP];
__device__ int   g_off[NEXP + 1];
__device__ int   g_ptok[NPAIR];
__device__ float g_pw  [NPAIR];
__device__ int   g_tok_pair[LSEQ * 2];
__device__ float g_h [(size_t)NPAIR * HIDDEN];   // 64 MB
__device__ float g_y2[(size_t)NPAIR * DMODEL];   // 16 MB

// ---------------- helpers ----------------
__device__ __forceinline__ uint32_t f2tf32(float x) {
    uint32_t r; asm("cvt.rna.tf32.f32 %0, %1;" : "=r"(r) : "f"(x)); return r;
}

__device__ __forceinline__ void mma8(float* d, const uint32_t* a, const uint32_t* b) {
    asm volatile(
        "mma.sync.aligned.m16n8k8.row.col.f32.tf32.tf32.f32 "
        "{%0,%1,%2,%3},{%4,%5,%6,%7},{%8,%9},{%0,%1,%2,%3};\n"
        : "+f"(d[0]), "+f"(d[1]), "+f"(d[2]), "+f"(d[3])
        : "r"(a[0]), "r"(a[1]), "r"(a[2]), "r"(a[3]), "r"(b[0]), "r"(b[1]));
}

#define KT 16

// split fp32 into hi/lo tf32 and store (swizzled) to shared
__device__ __forceinline__ void split_store(float* hi, float* lo, int row, int g, float4 v) {
    int ch = (g ^ ((row >> 1) & 3)) << 2;
    float4 h, l;
    h.x = __uint_as_float(f2tf32(v.x)); l.x = __uint_as_float(f2tf32(v.x - h.x));
    h.y = __uint_as_float(f2tf32(v.y)); l.y = __uint_as_float(f2tf32(v.y - h.y));
    h.z = __uint_as_float(f2tf32(v.z)); l.z = __uint_as_float(f2tf32(v.z - h.z));
    h.w = __uint_as_float(f2tf32(v.w)); l.w = __uint_as_float(f2tf32(v.w - h.w));
    *(float4*)(hi + row * KT + ch) = h;
    *(float4*)(lo + row * KT + ch) = l;
}

// ---------------- tensor-core GEMM (tf32x3): C = epi(A @ W^T) ----------------
// A: (M,K) row-major stride lda; W: (N,K) row-major stride K.
// EPI: 0 store, 1 gelu, 2 +addsrc, 3 softplus(+bias)
// MODE: 0 plain, 1 moe-gemm1 (gather A rows by ptok, per-expert W/out rows),
//       2 moe-gemm2 (contiguous per-expert A rows, per-expert W)
template<int EPI, int MODE>
__global__ void __launch_bounds__(256, 2) mma_gemm(
    const float* __restrict__ A, int lda,
    const float* __restrict__ Wg, int K,
    float* __restrict__ C, int ldc,
    int M, int N,
    const float* __restrict__ bias,
    const float* __restrict__ addsrc, int ldadd,
    const int* __restrict__ off, const int* __restrict__ ptok)
{
    int base = 0, rows = M;
    const float* W = Wg;
    if (MODE != 0) {
        int e = blockIdx.z;
        base = off[e];
        rows = off[e + 1] - base;
        W = Wg + (size_t)e * N * K;
    }
    int m0 = blockIdx.x * 128;
    if (m0 >= rows) return;
    int n0 = blockIdx.y * 128;

    __shared__ float sAhi[128 * KT], sAlo[128 * KT], sBhi[128 * KT], sBlo[128 * KT];

    int tid = threadIdx.x;
    int wid = tid >> 5, lane = tid & 31;
    int lr = lane >> 2, lc = lane & 3;
    int warp_m = wid & 1, warp_n = wid >> 1;

    // global load mapping: this thread owns A rows arow0/arow1, k-group kg
    int arow0 = tid >> 2;
    int arow1 = arow0 + 64;
    int kg = tid & 3;

    const float *Arow0, *Arow1;
    bool aok0, aok1;
    if (MODE == 1) {
        int r0 = m0 + arow0, r1 = m0 + arow1;
        aok0 = r0 < rows; aok1 = r1 < rows;
        int t0 = aok0 ? ptok[base + r0] : 0;
        int t1 = aok1 ? ptok[base + r1] : 0;
        Arow0 = A + (size_t)t0 * lda;
        Arow1 = A + (size_t)t1 * lda;
    } else if (MODE == 2) {
        int r0 = m0 + arow0, r1 = m0 + arow1;
        aok0 = r0 < rows; aok1 = r1 < rows;
        Arow0 = A + (size_t)(base + (aok0 ? r0 : 0)) * lda;
        Arow1 = A + (size_t)(base + (aok1 ? r1 : 0)) * lda;
    } else {
        aok0 = true; aok1 = true;
        Arow0 = A + (size_t)(m0 + arow0) * lda;
        Arow1 = A + (size_t)(m0 + arow1) * lda;
    }
    const float* Brow0 = W + (size_t)(n0 + arow0) * K;
    const float* Brow1 = W + (size_t)(n0 + arow1) * K;

    const float4 z4 = make_float4(0.f, 0.f, 0.f, 0.f);
    float4 ra0, ra1, rb0, rb1;
    ra0 = aok0 ? *(const float4*)(Arow0 + kg * 4) : z4;
    ra1 = aok1 ? *(const float4*)(Arow1 + kg * 4) : z4;
    rb0 = *(const float4*)(Brow0 + kg * 4);
    rb1 = *(const float4*)(Brow1 + kg * 4);

    float acc[4][4][4];
    #pragma unroll
    for (int i = 0; i < 4; i++)
        #pragma unroll
        for (int j = 0; j < 4; j++)
            #pragma unroll
            for (int r = 0; r < 4; r++) acc[i][j][r] = 0.f;

    const uint32_t* uAhi = (const uint32_t*)sAhi;
    const uint32_t* uAlo = (const uint32_t*)sAlo;
    const uint32_t* uBhi = (const uint32_t*)sBhi;
    const uint32_t* uBlo = (const uint32_t*)sBlo;

    for (int kt = 0; kt < K; kt += KT) {
        __syncthreads();
        split_store(sAhi, sAlo, arow0, kg, ra0);
        split_store(sAhi, sAlo, arow1, kg, ra1);
        split_store(sBhi, sBlo, arow0, kg, rb0);
        split_store(sBhi, sBlo, arow1, kg, rb1);
        __syncthreads();
        int knext = kt + KT;
        if (knext < K) {
            ra0 = aok0 ? *(const float4*)(Arow0 + knext + kg * 4) : z4;
            ra1 = aok1 ? *(const float4*)(Arow1 + knext + kg * 4) : z4;
            rb0 = *(const float4*)(Brow0 + knext + kg * 4);
            rb1 = *(const float4*)(Brow1 + knext + kg * 4);
        }
        #pragma unroll
        for (int k8 = 0; k8 < 16; k8 += 8) {
            uint32_t bh[4][2], bl[4][2];
            #pragma unroll
            for (int in = 0; in < 4; in++) {
                int n = warp_n * 32 + in * 8 + lr;
                int q = ((n >> 1) & 3) << 2;
                int i0 = n * KT + ((k8 + lc) ^ q);
                int i1 = n * KT + ((k8 + lc + 4) ^ q);
                bh[in][0] = uBhi[i0]; bh[in][1] = uBhi[i1];
                bl[in][0] = uBlo[i0]; bl[in][1] = uBlo[i1];
            }
            #pragma unroll
            for (int im = 0; im < 4; im++) {
                int m = warp_m * 64 + im * 16 + lr;
                int m2 = m + 8;
                int q1 = ((m >> 1) & 3) << 2;
                int q2 = ((m2 >> 1) & 3) << 2;
                int i0 = m  * KT + ((k8 + lc) ^ q1);
                int i1 = m2 * KT + ((k8 + lc) ^ q2);
                int i2 = m  * KT + ((k8 + lc + 4) ^ q1);
                int i3 = m2 * KT + ((k8 + lc + 4) ^ q2);
                uint32_t ah[4] = { uAhi[i0], uAhi[i1], uAhi[i2], uAhi[i3] };
                uint32_t al[4] = { uAlo[i0], uAlo[i1], uAlo[i2], uAlo[i3] };
                #pragma unroll
                for (int in = 0; in < 4; in++) {
                    mma8(acc[im][in], ah, bh[in]);
                    mma8(acc[im][in], ah, bl[in]);
                    mma8(acc[im][in], al, bh[in]);
                }
            }
        }
    }

    // epilogue
    #pragma unroll
    for (int im = 0; im < 4; im++) {
        #pragma unroll
        for (int half = 0; half < 2; half++) {
            int m = m0 + warp_m * 64 + im * 16 + lr + half * 8;
            if (m >= rows) continue;
            size_t crow = (size_t)(base + m) * ldc;
            #pragma unroll
            for (int in = 0; in < 4; in++) {
                int n = n0 + warp_n * 32 + in * 8 + lc * 2;
                float v0 = acc[im][in][half * 2];
                float v1 = acc[im][in][half * 2 + 1];
                if (EPI == 1) {
                    v0 = 0.5f * v0 * (1.0f + erff(v0 * 0.70710678118654752f));
                    v1 = 0.5f * v1 * (1.0f + erff(v1 * 0.70710678118654752f));
                } else if (EPI == 2) {
                    v0 += addsrc[(size_t)m * ldadd + n];
                    v1 += addsrc[(size_t)m * ldadd + n + 1];
                } else if (EPI == 3) {
                    float z0 = v0 + bias[n], z1 = v1 + bias[n + 1];
                    v0 = (z0 > 20.f) ? z0 : log1pf(__expf(z0));
                    v1 = (z1 > 20.f) ? z1 : log1pf(__expf(z1));
                }
                *(float2*)(C + crow + n) = make_float2(v0, v1);
            }
        }
    }
}

// ---------------- rmsnorm (row = 1024) ----------------
__global__ void rmsnorm_kernel(const float* __restrict__ x, float* __restrict__ o)
{
    int row = blockIdx.x;
    const float* xp = x + (size_t)row * DMODEL;
    float s = 0.f;
    for (int k = threadIdx.x; k < DMODEL; k += 256) { float v = xp[k]; s += v * v; }
    __shared__ float sh[8];
    #pragma unroll
    for (int off = 16; off; off >>= 1) s += __shfl_xor_sync(0xffffffffu, s, off);
    if ((threadIdx.x & 31) == 0) sh[threadIdx.x >> 5] = s;
    __syncthreads();
    if (threadIdx.x < 8) {
        float v = sh[threadIdx.x];
        #pragma unroll
        for (int off = 4; off; off >>= 1) v += __shfl_xor_sync(0xffu, v, off);
        if (threadIdx.x == 0) sh[0] = v;
    }
    __syncthreads();
    float scale = 32.0f / fmaxf(sqrtf(sh[0]), 1e-12f);
    float* op = o + (size_t)row * DMODEL;
    for (int k = threadIdx.x; k < DMODEL; k += 256) op[k] = xp[k] * scale;
}

// ---------------- split-K SIMT GEMM for skinny x_proj ----------------
__global__ void __launch_bounds__(256) gemm_sk(
    const float* __restrict__ A, int lda,
    const float* __restrict__ W, int ldw,
    float* __restrict__ Cpart, int ldc,
    int M, int N, int kchunk)
{
    int koff = blockIdx.z * kchunk;
    float* C = Cpart + (size_t)blockIdx.z * M * ldc;
    __shared__ float As[16][68];
    __shared__ float Bs[16][68];
    int tid = threadIdx.x;
    int m0 = blockIdx.x * 64, n0 = blockIdx.y * 64;
    int tx = tid & 15, ty = tid >> 4;
    int lr = tid >> 2;
    int lk = (tid & 3) << 2;
    int am = m0 + lr;
    int wn = n0 + lr;
    bool a_ok = am < M;
    bool w_ok = wn < N;
    const float* Arow = A + (size_t)(a_ok ? am : 0) * lda + koff;
    const float* Wrow = W + (size_t)(w_ok ? wn : 0) * ldw + koff;
    float acc[4][4] = {};
    for (int k0 = 0; k0 < kchunk; k0 += 16) {
        float4 av = a_ok ? *(const float4*)(Arow + k0 + lk) : make_float4(0, 0, 0, 0);
        float4 wv = w_ok ? *(const float4*)(Wrow + k0 + lk) : make_float4(0, 0, 0, 0);
        __syncthreads();
        As[lk][lr] = av.x; As[lk + 1][lr] = av.y; As[lk + 2][lr] = av.z; As[lk + 3][lr] = av.w;
        Bs[lk][lr] = wv.x; Bs[lk + 1][lr] = wv.y; Bs[lk + 2][lr] = wv.z; Bs[lk + 3][lr] = wv.w;
        __syncthreads();
        #pragma unroll
        for (int k = 0; k < 16; k++) {
            float a[4], b[4];
            #pragma unroll
            for (int i = 0; i < 4; i++) a[i] = As[k][ty * 4 + i];
            #pragma unroll
            for (int j = 0; j < 4; j++) b[j] = Bs[k][tx * 4 + j];
            #pragma unroll
            for (int i = 0; i < 4; i++)
                #pragma unroll
                for (int j = 0; j < 4; j++)
                    acc[i][j] += a[i] * b[j];
        }
    }
    #pragma unroll
    for (int i = 0; i < 4; i++) {
        int m = m0 + ty * 4 + i;
        if (m >= M) continue;
        #pragma unroll
        for (int j = 0; j < 4; j++) {
            int n = n0 + tx * 4 + j;
            if (n >= N) continue;
            C[(size_t)m * ldc + n] = acc[i][j];
        }
    }
}

__global__ void reduce4(const float* __restrict__ p, float* __restrict__ o, int n)
{
    int i = blockIdx.x * 256 + threadIdx.x;
    if (i < n) o[i] = (p[i] + p[i + n]) + (p[i + 2 * n] + p[i + 3 * n]);
}

// ---------------- causal depthwise conv(4) + silu ----------------
__global__ void conv_silu(const float* __restrict__ xr, const float* __restrict__ cw,
                          const float* __restrict__ cb, float* __restrict__ u)
{
    int idx = blockIdx.x * 256 + threadIdx.x;
    int t = idx >> 11, d = idx & (DINNER - 1);
    float w0 = cw[d * 4], w1 = cw[d * 4 + 1], w2 = cw[d * 4 + 2], w3 = cw[d * 4 + 3];
    float s = cb[d];
    const float* col = xr + d;
    if (t >= 3) s += col[(size_t)(t - 3) * (2 * DINNER)] * w0;
    if (t >= 2) s += col[(size_t)(t - 2) * (2 * DINNER)] * w1;
    if (t >= 1) s += col[(size_t)(t - 1) * (2 * DINNER)] * w2;
    s += col[(size_t)t * (2 * DINNER)] * w3;
    u[idx] = s / (1.f + __expf(-s));
}

// ---------------- selective scan ----------------
__global__ void scan_kernel(const float* __restrict__ delta,
                            const float* __restrict__ u,
                            const float* __restrict__ xdbl,
                            const float* __restrict__ A_log,
                            const float* __restrict__ Dvec,
                            const float* __restrict__ xr,
                            float* __restrict__ y)
{
    int lane16 = threadIdx.x & 15;
    int ch = threadIdx.x >> 4;
    int d = blockIdx.x * 8 + ch;
    float A = -__expf(A_log[d * DSTATE + lane16]);
    float Dd = Dvec[d];
    float h = 0.f;
    __shared__ float sB[32][16], sC[32][16], sdl[32][8], su[32][8], sre[32][8];
    for (int t0 = 0; t0 < LSEQ; t0 += 32) {
        __syncthreads();
        for (int i = threadIdx.x; i < 512; i += 128) {
            int tt = i >> 4, n = i & 15;
            const float* xb = xdbl + (size_t)(t0 + tt) * XDBL;
            sB[tt][n] = xb[DTRANK + n];
            sC[tt][n] = xb[DTRANK + DSTATE + n];
        }
        for (int i = threadIdx.x; i < 256; i += 128) {
            int tt = i >> 3, c = i & 7;
            int dd = blockIdx.x * 8 + c;
            size_t off = (size_t)(t0 + tt) * DINNER + dd;
            sdl[tt][c] = delta[off];
            su[tt][c]  = u[off];
            sre[tt][c] = xr[(size_t)(t0 + tt) * (2 * DINNER) + DINNER + dd];
        }
        __syncthreads();
        for (int tt = 0; tt < 32; tt++) {
            float dl = sdl[tt][ch];
            float uu = su[tt][ch];
            float dA = __expf(dl * A);
            h = dA * h + dl * sB[tt][lane16] * uu;
            float p = h * sC[tt][lane16];
            #pragma unroll
            for (int o = 8; o; o >>= 1) p += __shfl_xor_sync(0xffffffffu, p, o, 16);
            if (lane16 == 0) {
                float yv = p + uu * Dd;
                float r = sre[tt][ch];
                yv *= r / (1.f + __expf(-r));
                y[(size_t)(t0 + tt) * DINNER + d] = yv;
            }
        }
    }
}

// ---------------- gating: GEMV + softmax + top-2 ----------------
__global__ void gate_topk(const float* __restrict__ X, const float* __restrict__ gw,
                          int* __restrict__ te, float* __restrict__ tv)
{
    __shared__ float sg[NEXP * DMODEL];
    for (int i = threadIdx.x; i < NEXP * DMODEL; i += 128) sg[i] = gw[i];
    __syncthreads();
    int warp = threadIdx.x >> 5, lane = threadIdx.x & 31;
    int t = blockIdx.x * 4 + warp;
    const float* xp = X + (size_t)t * DMODEL;
    float acc[NEXP] = {};
    for (int k = lane; k < DMODEL; k += 32) {
        float xv = xp[k];
        #pragma unroll
        for (int e = 0; e < NEXP; e++) acc[e] += xv * sg[e * DMODEL + k];
    }
    #pragma unroll
    for (int e = 0; e < NEXP; e++)
        #pragma unroll
        for (int o = 16; o; o >>= 1) acc[e] += __shfl_xor_sync(0xffffffffu, acc[e], o);
    if (lane == 0) {
        float m = acc[0];
        #pragma unroll
        for (int e = 1; e < NEXP; e++) m = fmaxf(m, acc[e]);
        float g[NEXP];
        #pragma unroll
        for (int e = 0; e < NEXP; e++) g[e] = __expf(acc[e] - m);
        int i0 = 0;
        #pragma unroll
        for (int e = 1; e < NEXP; e++) if (g[e] > g[i0]) i0 = e;
        int i1 = (i0 == 0) ? 1 : 0;
        #pragma unroll
        for (int e = 0; e < NEXP; e++) if (e != i0 && g[e] > g[i1]) i1 = e;
        float inv = 1.f / (g[i0] + g[i1]);
        te[t * 2] = i0; te[t * 2 + 1] = i1;
        tv[t * 2] = g[i0] * inv; tv[t * 2 + 1] = g[i1] * inv;
    }
}

// ---------------- routing ----------------
__global__ void route_zero(int* cnt, int* cur)
{
    if (threadIdx.x < NEXP) { cnt[threadIdx.x] = 0; cur[threadIdx.x] = 0; }
}
__global__ void route_count(const int* __restrict__ te, int* cnt)
{
    int t = blockIdx.x * 256 + threadIdx.x;
    atomicAdd(&cnt[te[t * 2]], 1);
    atomicAdd(&cnt[te[t * 2 + 1]], 1);
}
__global__ void route_offsets(const int* __restrict__ cnt, int* off)
{
    int s = 0;
    for (int e = 0; e < NEXP; e++) { off[e] = s; s += cnt[e]; }
    off[NEXP] = s;
}
__global__ void route_scatter(const int* __restrict__ te, const float* __restrict__ tv,
                              const int* __restrict__ off, int* cur,
                              int* ptok, float* pw, int* tok_pair)
{
    int t = blockIdx.x * 256 + threadIdx.x;
    #pragma unroll
    for (int k = 0; k < 2; k++) {
        int e = te[t * 2 + k];
        int pos = atomicAdd(&cur[e], 1);
        int p = off[e] + pos;
        ptok[p] = t;
        pw[p] = tv[t * 2 + k];
        tok_pair[t * 2 + k] = p;
    }
}

// ---------------- final combine ----------------
__global__ void moe_combine(const float* __restrict__ x, const float* __restrict__ y2,
                            const int* __restrict__ tok_pair, const float* __restrict__ pw,
                            float* __restrict__ out)
{
    int i = blockIdx.x * 256 + threadIdx.x;
    int t = i >> 10, n = i & (DMODEL - 1);
    int p0 = tok_pair[t * 2], p1 = tok_pair[t * 2 + 1];
    out[i] = x[i] + pw[p0] * y2[(size_t)p0 * DMODEL + n]
                  + pw[p1] * y2[(size_t)p1 * DMODEL + n];
}

// ---------------- launch ----------------
extern "C" void kernel_launch(void* const* d_in, const int* in_sizes, int n_in,
                              void* d_out, int out_size)
{
    (void)in_sizes; (void)n_in; (void)out_size;
    const float* x          = (const float*)d_in[0];
    const float* in_proj_w  = (const float*)d_in[1];
    const float* conv_w     = (const float*)d_in[2];
    const float* conv_b     = (const float*)d_in[3];
    const float* x_proj_w   = (const float*)d_in[4];
    const float* dt_proj_w  = (const float*)d_in[5];
    const float* dt_proj_b  = (const float*)d_in[6];
    const float* A_log      = (const float*)d_in[7];
    const float* Dvec       = (const float*)d_in[8];
    const float* out_proj_w = (const float*)d_in[9];
    const float* gate_w     = (const float*)d_in[10];
    const float* w1         = (const float*)d_in[11];
    const float* w2         = (const float*)d_in[12];
    float* out = (float*)d_out;

    float *p_xn, *p_xr, *p_u, *p_xdbl, *p_xp, *p_delta, *p_y, *p_xm2, *p_xm2n, *p_tv, *p_pw, *p_h, *p_y2;
    int *p_te, *p_cnt, *p_cur, *p_off, *p_ptok, *p_tp;
    cudaGetSymbolAddress((void**)&p_xn, g_xn);
    cudaGetSymbolAddress((void**)&p_xr, g_xr);
    cudaGetSymbolAddress((void**)&p_u, g_u);
    cudaGetSymbolAddress((void**)&p_xdbl, g_xdbl);
    cudaGetSymbolAddress((void**)&p_xp, g_xp);
    cudaGetSymbolAddress((void**)&p_delta, g_delta);
    cudaGetSymbolAddress((void**)&p_y, g_y);
    cudaGetSymbolAddress((void**)&p_xm2, g_xm2);
    cudaGetSymbolAddress((void**)&p_xm2n, g_xm2n);
    cudaGetSymbolAddress((void**)&p_te, g_top_e);
    cudaGetSymbolAddress((void**)&p_tv, g_top_v);
    cudaGetSymbolAddress((void**)&p_cnt, g_cnt);
    cudaGetSymbolAddress((void**)&p_cur, g_cur);
    cudaGetSymbolAddress((void**)&p_off, g_off);
    cudaGetSymbolAddress((void**)&p_ptok, g_ptok);
    cudaGetSymbolAddress((void**)&p_pw, g_pw);
    cudaGetSymbolAddress((void**)&p_tp, g_tok_pair);
    cudaGetSymbolAddress((void**)&p_h, g_h);
    cudaGetSymbolAddress((void**)&p_y2, g_y2);

    // 1. xn = rmsnorm(x)
    rmsnorm_kernel<<<LSEQ, 256>>>(x, p_xn);
    // 2. xr = xn @ in_proj_w^T   (2048 x 4096, K=1024) [tensor]
    mma_gemm<0, 0><<<dim3(16, 32), 256>>>(p_xn, DMODEL, in_proj_w, DMODEL,
                                          p_xr, 2 * DINNER, LSEQ, 2 * DINNER,
                                          nullptr, nullptr, 0, nullptr, nullptr);
    // 3. u = silu(causal_conv(xm) + b)
    conv_silu<<<(LSEQ * DINNER) / 256, 256>>>(p_xr, conv_w, conv_b, p_u);
    // 4. x_dbl = u @ x_proj_w^T  (2048 x 96, K=2048) [split-K=4 SIMT]
    gemm_sk<<<dim3(32, 2, 4), 256>>>(p_u, DINNER, x_proj_w, DINNER,
                                     p_xp, XDBL, LSEQ, XDBL, DINNER / 4);
    reduce4<<<(LSEQ * XDBL + 255) / 256, 256>>>(p_xp, p_xdbl, LSEQ * XDBL);
    // 5. delta = softplus(dt @ dt_proj_w^T + b)  (2048 x 2048, K=64) [tensor]
    mma_gemm<3, 0><<<dim3(16, 16), 256>>>(p_xdbl, XDBL, dt_proj_w, DTRANK,
                                          p_delta, DINNER, LSEQ, DINNER,
                                          dt_proj_b, nullptr, 0, nullptr, nullptr);
    // 6. selective scan
    scan_kernel<<<DINNER / 8, 128>>>(p_delta, p_u, p_xdbl, A_log, Dvec, p_xr, p_y);
    // 7. xm2 = y @ out_proj_w^T + xn  (2048 x 1024, K=2048) [tensor]
    mma_gemm<2, 0><<<dim3(16, 8), 256>>>(p_y, DINNER, out_proj_w, DINNER,
                                         p_xm2, DMODEL, LSEQ, DMODEL,
                                         nullptr, p_xn, DMODEL, nullptr, nullptr);
    // 8. xm2n = rmsnorm(xm2)
    rmsnorm_kernel<<<LSEQ, 256>>>(p_xm2, p_xm2n);
    // 9. gating + top-2
    gate_topk<<<LSEQ / 4, 128>>>(p_xm2n, gate_w, p_te, p_tv);
    // 10. routing
    route_zero<<<1, 32>>>(p_cnt, p_cur);
    route_count<<<LSEQ / 256, 256>>>(p_te, p_cnt);
    route_offsets<<<1, 1>>>(p_cnt, p_off);
    route_scatter<<<LSEQ / 256, 256>>>(p_te, p_tv, p_off, p_cur, p_ptok, p_pw, p_tp);
    // 11. expert GEMMs [tensor]
    mma_gemm<1, 1><<<dim3(32, 32, NEXP), 256>>>(p_xm2n, DMODEL, w1, DMODEL,
                                                p_h, HIDDEN, 0, HIDDEN,
                                                nullptr, nullptr, 0, p_off, p_ptok);
    mma_gemm<0, 2><<<dim3(32, 8, NEXP), 256>>>(p_h, HIDDEN, w2, HIDDEN,
                                               p_y2, DMODEL, 0, DMODEL,
                                               nullptr, nullptr, 0, p_off, nullptr);
    moe_combine<<<(LSEQ * DMODEL) / 256, 256>>>(x, p_y2, p_tp, p_pw, out);
}

// round 3
// speedup vs baseline: 2.1119x; 1.3907x over previous
#include <cuda_runtime.h>
#include <cuda_bf16.h>
#include <math.h>
#include <stdint.h>

// ---------------- problem constants ----------------
#define LSEQ   2048
#define DMODEL 1024
#define DINNER 2048
#define DSTATE 16
#define DTRANK 64
#define XDBL   96      // dt_rank + 2*d_state
#define NEXP   8
#define HIDDEN 4096
#define NPAIR  4096    // L * top-k

// ---------------- scratch (static device, no allocs) ----------------
__device__ float g_xn   [LSEQ * DMODEL];
__device__ float g_xr   [LSEQ * 2 * DINNER];
__device__ float g_u    [LSEQ * DINNER];
__device__ float g_xdbl [LSEQ * XDBL];
__device__ float g_xp   [4 * LSEQ * XDBL];
__device__ float g_delta[LSEQ * DINNER];
__device__ float g_y    [LSEQ * DINNER];
__device__ float g_xm2  [LSEQ * DMODEL];
__device__ float g_xm2n [LSEQ * DMODEL];
__device__ int   g_top_e[LSEQ * 2];
__device__ float g_top_v[LSEQ * 2];
__device__ int   g_cnt[NEXP];
__device__ int   g_cur[NEXP];
__device__ int   g_off[NEXP + 1];
__device__ int   g_ptok[NPAIR];
__device__ float g_pw  [NPAIR];
__device__ int   g_tok_pair[LSEQ * 2];
__device__ float g_h [(size_t)NPAIR * HIDDEN];   // 64 MB
__device__ float g_y2[(size_t)NPAIR * DMODEL];   // 16 MB

// ---------------- bf16 split helpers ----------------
__device__ __forceinline__ uint32_t pack_bf2(float a, float b, float& ra, float& rb)
{
    __nv_bfloat162 p;
    p.x = __float2bfloat16_rn(a);
    p.y = __float2bfloat16_rn(b);
    ra = a - __bfloat162float(p.x);
    rb = b - __bfloat162float(p.y);
    return *(uint32_t*)&p;
}
__device__ __forceinline__ uint32_t pack_bf2n(float a, float b)
{
    __nv_bfloat162 p;
    p.x = __float2bfloat16_rn(a);
    p.y = __float2bfloat16_rn(b);
    return *(uint32_t*)&p;
}

// store one float4 (k = 4*kg .. 4*kg+3) of row into hi/lo smem tiles.
// layout: row stride = 8 words (16 bf16); physical word = logical ^ (row&7).
__device__ __forceinline__ void split_store_bf(uint32_t* hi, uint32_t* lo,
                                               int row, int kg, float4 v)
{
    float r0, r1, r2, r3;
    uint32_t h0 = pack_bf2(v.x, v.y, r0, r1);
    uint32_t h1 = pack_bf2(v.z, v.w, r2, r3);
    uint32_t l0 = pack_bf2n(r0, r1);
    uint32_t l1 = pack_bf2n(r2, r3);
    int r = row & 7;
    int w0 = (2 * kg) ^ r;
    int aw = w0 & ~1;
    uint2 dh = (r & 1) ? make_uint2(h1, h0) : make_uint2(h0, h1);
    uint2 dl = (r & 1) ? make_uint2(l1, l0) : make_uint2(l0, l1);
    *(uint2*)(hi + row * 8 + aw) = dh;
    *(uint2*)(lo + row * 8 + aw) = dl;
}

__device__ __forceinline__ uint32_t fragld(const uint32_t* s, int row, int w)
{
    return s[row * 8 + (w ^ (row & 7))];
}

__device__ __forceinline__ void mma16(float* d, const uint32_t* a, const uint32_t* b)
{
    asm volatile(
        "mma.sync.aligned.m16n8k16.row.col.f32.bf16.bf16.f32 "
        "{%0,%1,%2,%3},{%4,%5,%6,%7},{%8,%9},{%0,%1,%2,%3};\n"
        : "+f"(d[0]), "+f"(d[1]), "+f"(d[2]), "+f"(d[3])
        : "r"(a[0]), "r"(a[1]), "r"(a[2]), "r"(a[3]), "r"(b[0]), "r"(b[1]));
}

#define KT 16

// ---------------- tensor-core GEMM (bf16x2, 3-term): C = epi(A @ W^T) ----------------
// A: (M,K) row-major stride lda; W: (N,K) row-major stride K.
// EPI: 0 store, 1 gelu, 2 +addsrc, 3 softplus(+bias)
// MODE: 0 plain, 1 moe-gemm1 (gather A rows via ptok), 2 moe-gemm2 (contiguous expert rows)
template<int EPI, int MODE>
__global__ void __launch_bounds__(256, 2) bmma_gemm(
    const float* __restrict__ A, int lda,
    const float* __restrict__ Wg, int K,
    float* __restrict__ C, int ldc,
    int M, int N,
    const float* __restrict__ bias,
    const float* __restrict__ addsrc, int ldadd,
    const int* __restrict__ off, const int* __restrict__ ptok)
{
    int base = 0, rows = M;
    const float* W = Wg;
    if (MODE != 0) {
        int e = blockIdx.z;
        base = off[e];
        rows = off[e + 1] - base;
        W = Wg + (size_t)e * N * K;
    }
    int m0 = blockIdx.x * 128;
    if (m0 >= rows) return;
    int n0 = blockIdx.y * 128;

    __shared__ __align__(16) uint32_t sAhi[128 * 8], sAlo[128 * 8];
    __shared__ __align__(16) uint32_t sBhi[128 * 8], sBlo[128 * 8];

    int tid = threadIdx.x;
    int wid = tid >> 5, lane = tid & 31;
    int lr = lane >> 2, lc = lane & 3;
    int warp_m = wid & 1, warp_n = wid >> 1;

    int arow0 = tid >> 2;        // 0..63
    int arow1 = arow0 + 64;
    int kg = tid & 3;            // float4 index within k16

    const float *Arow0, *Arow1;
    bool aok0, aok1;
    if (MODE == 1) {
        int r0 = m0 + arow0, r1 = m0 + arow1;
        aok0 = r0 < rows; aok1 = r1 < rows;
        int t0 = aok0 ? ptok[base + r0] : 0;
        int t1 = aok1 ? ptok[base + r1] : 0;
        Arow0 = A + (size_t)t0 * lda;
        Arow1 = A + (size_t)t1 * lda;
    } else if (MODE == 2) {
        int r0 = m0 + arow0, r1 = m0 + arow1;
        aok0 = r0 < rows; aok1 = r1 < rows;
        Arow0 = A + (size_t)(base + (aok0 ? r0 : 0)) * lda;
        Arow1 = A + (size_t)(base + (aok1 ? r1 : 0)) * lda;
    } else {
        aok0 = true; aok1 = true;
        Arow0 = A + (size_t)(m0 + arow0) * lda;
        Arow1 = A + (size_t)(m0 + arow1) * lda;
    }
    const float* Brow0 = W + (size_t)(n0 + arow0) * K;
    const float* Brow1 = W + (size_t)(n0 + arow1) * K;

    const float4 z4 = make_float4(0.f, 0.f, 0.f, 0.f);
    float4 ra0, ra1, rb0, rb1;
    ra0 = aok0 ? *(const float4*)(Arow0 + kg * 4) : z4;
    ra1 = aok1 ? *(const float4*)(Arow1 + kg * 4) : z4;
    rb0 = *(const float4*)(Brow0 + kg * 4);
    rb1 = *(const float4*)(Brow1 + kg * 4);

    float acc[4][4][4];
    #pragma unroll
    for (int i = 0; i < 4; i++)
        #pragma unroll
        for (int j = 0; j < 4; j++)
            #pragma unroll
            for (int r = 0; r < 4; r++) acc[i][j][r] = 0.f;

    for (int kt = 0; kt < K; kt += KT) {
        __syncthreads();
        split_store_bf(sAhi, sAlo, arow0, kg, ra0);
        split_store_bf(sAhi, sAlo, arow1, kg, ra1);
        split_store_bf(sBhi, sBlo, arow0, kg, rb0);
        split_store_bf(sBhi, sBlo, arow1, kg, rb1);
        __syncthreads();
        int knext = kt + KT;
        if (knext < K) {
            ra0 = aok0 ? *(const float4*)(Arow0 + knext + kg * 4) : z4;
            ra1 = aok1 ? *(const float4*)(Arow1 + knext + kg * 4) : z4;
            rb0 = *(const float4*)(Brow0 + knext + kg * 4);
            rb1 = *(const float4*)(Brow1 + knext + kg * 4);
        }
        // B fragments
        uint32_t bh[4][2], bl[4][2];
        #pragma unroll
        for (int in = 0; in < 4; in++) {
            int n = warp_n * 32 + in * 8 + lr;
            bh[in][0] = fragld(sBhi, n, lc);
            bh[in][1] = fragld(sBhi, n, lc + 4);
            bl[in][0] = fragld(sBlo, n, lc);
            bl[in][1] = fragld(sBlo, n, lc + 4);
        }
        #pragma unroll
        for (int im = 0; im < 4; im++) {
            int m = warp_m * 64 + im * 16 + lr;
            uint32_t ah[4] = { fragld(sAhi, m, lc),     fragld(sAhi, m + 8, lc),
                               fragld(sAhi, m, lc + 4), fragld(sAhi, m + 8, lc + 4) };
            uint32_t al[4] = { fragld(sAlo, m, lc),     fragld(sAlo, m + 8, lc),
                               fragld(sAlo, m, lc + 4), fragld(sAlo, m + 8, lc + 4) };
            #pragma unroll
            for (int in = 0; in < 4; in++) {
                mma16(acc[im][in], ah, bh[in]);
                mma16(acc[im][in], ah, bl[in]);
                mma16(acc[im][in], al, bh[in]);
            }
        }
    }

    // epilogue
    #pragma unroll
    for (int im = 0; im < 4; im++) {
        #pragma unroll
        for (int half = 0; half < 2; half++) {
            int m = m0 + warp_m * 64 + im * 16 + lr + half * 8;
            if (m >= rows) continue;
            size_t crow = (size_t)(base + m) * ldc;
            #pragma unroll
            for (int in = 0; in < 4; in++) {
                int n = n0 + warp_n * 32 + in * 8 + lc * 2;
                float v0 = acc[im][in][half * 2];
                float v1 = acc[im][in][half * 2 + 1];
                if (EPI == 1) {
                    v0 = 0.5f * v0 * (1.0f + erff(v0 * 0.70710678118654752f));
                    v1 = 0.5f * v1 * (1.0f + erff(v1 * 0.70710678118654752f));
                } else if (EPI == 2) {
                    v0 += addsrc[(size_t)m * ldadd + n];
                    v1 += addsrc[(size_t)m * ldadd + n + 1];
                } else if (EPI == 3) {
                    float z0 = v0 + bias[n], z1 = v1 + bias[n + 1];
                    v0 = (z0 > 20.f) ? z0 : log1pf(__expf(z0));
                    v1 = (z1 > 20.f) ? z1 : log1pf(__expf(z1));
                }
                *(float2*)(C + crow + n) = make_float2(v0, v1);
            }
        }
    }
}

// ---------------- rmsnorm (row = 1024) ----------------
__global__ void rmsnorm_kernel(const float* __restrict__ x, float* __restrict__ o)
{
    int row = blockIdx.x;
    const float* xp = x + (size_t)row * DMODEL;
    float s = 0.f;
    for (int k = threadIdx.x; k < DMODEL; k += 256) { float v = xp[k]; s += v * v; }
    __shared__ float sh[8];
    #pragma unroll
    for (int off = 16; off; off >>= 1) s += __shfl_xor_sync(0xffffffffu, s, off);
    if ((threadIdx.x & 31) == 0) sh[threadIdx.x >> 5] = s;
    __syncthreads();
    if (threadIdx.x < 8) {
        float v = sh[threadIdx.x];
        #pragma unroll
        for (int off = 4; off; off >>= 1) v += __shfl_xor_sync(0xffu, v, off);
        if (threadIdx.x == 0) sh[0] = v;
    }
    __syncthreads();
    float scale = 32.0f / fmaxf(sqrtf(sh[0]), 1e-12f);
    float* op = o + (size_t)row * DMODEL;
    for (int k = threadIdx.x; k < DMODEL; k += 256) op[k] = xp[k] * scale;
}

// ---------------- split-K SIMT GEMM for skinny x_proj ----------------
__global__ void __launch_bounds__(256) gemm_sk(
    const float* __restrict__ A, int lda,
    const float* __restrict__ W, int ldw,
    float* __restrict__ Cpart, int ldc,
    int M, int N, int kchunk)
{
    int koff = blockIdx.z * kchunk;
    float* C = Cpart + (size_t)blockIdx.z * M * ldc;
    __shared__ float As[16][68];
    __shared__ float Bs[16][68];
    int tid = threadIdx.x;
    int m0 = blockIdx.x * 64, n0 = blockIdx.y * 64;
    int tx = tid & 15, ty = tid >> 4;
    int lr = tid >> 2;
    int lk = (tid & 3) << 2;
    int am = m0 + lr;
    int wn = n0 + lr;
    bool a_ok = am < M;
    bool w_ok = wn < N;
    const float* Arow = A + (size_t)(a_ok ? am : 0) * lda + koff;
    const float* Wrow = W + (size_t)(w_ok ? wn : 0) * ldw + koff;
    float acc[4][4] = {};
    for (int k0 = 0; k0 < kchunk; k0 += 16) {
        float4 av = a_ok ? *(const float4*)(Arow + k0 + lk) : make_float4(0, 0, 0, 0);
        float4 wv = w_ok ? *(const float4*)(Wrow + k0 + lk) : make_float4(0, 0, 0, 0);
        __syncthreads();
        As[lk][lr] = av.x; As[lk + 1][lr] = av.y; As[lk + 2][lr] = av.z; As[lk + 3][lr] = av.w;
        Bs[lk][lr] = wv.x; Bs[lk + 1][lr] = wv.y; Bs[lk + 2][lr] = wv.z; Bs[lk + 3][lr] = wv.w;
        __syncthreads();
        #pragma unroll
        for (int k = 0; k < 16; k++) {
            float a[4], b[4];
            #pragma unroll
            for (int i = 0; i < 4; i++) a[i] = As[k][ty * 4 + i];
            #pragma unroll
            for (int j = 0; j < 4; j++) b[j] = Bs[k][tx * 4 + j];
            #pragma unroll
            for (int i = 0; i < 4; i++)
                #pragma unroll
                for (int j = 0; j < 4; j++)
                    acc[i][j] += a[i] * b[j];
        }
    }
    #pragma unroll
    for (int i = 0; i < 4; i++) {
        int m = m0 + ty * 4 + i;
        if (m >= M) continue;
        #pragma unroll
        for (int j = 0; j < 4; j++) {
            int n = n0 + tx * 4 + j;
            if (n >= N) continue;
            C[(size_t)m * ldc + n] = acc[i][j];
        }
    }
}

__global__ void reduce4(const float* __restrict__ p, float* __restrict__ o, int n)
{
    int i = blockIdx.x * 256 + threadIdx.x;
    if (i < n) o[i] = (p[i] + p[i + n]) + (p[i + 2 * n] + p[i + 3 * n]);
}

// ---------------- causal depthwise conv(4) + silu ----------------
__global__ void conv_silu(const float* __restrict__ xr, const float* __restrict__ cw,
                          const float* __restrict__ cb, float* __restrict__ u)
{
    int idx = blockIdx.x * 256 + threadIdx.x;
    int t = idx >> 11, d = idx & (DINNER - 1);
    float w0 = cw[d * 4], w1 = cw[d * 4 + 1], w2 = cw[d * 4 + 2], w3 = cw[d * 4 + 3];
    float s = cb[d];
    const float* col = xr + d;
    if (t >= 3) s += col[(size_t)(t - 3) * (2 * DINNER)] * w0;
    if (t >= 2) s += col[(size_t)(t - 2) * (2 * DINNER)] * w1;
    if (t >= 1) s += col[(size_t)(t - 1) * (2 * DINNER)] * w2;
    s += col[(size_t)t * (2 * DINNER)] * w3;
    u[idx] = s / (1.f + __expf(-s));
}

// ---------------- selective scan ----------------
__global__ void scan_kernel(const float* __restrict__ delta,
                            const float* __restrict__ u,
                            const float* __restrict__ xdbl,
                            const float* __restrict__ A_log,
                            const float* __restrict__ Dvec,
                            const float* __restrict__ xr,
                            float* __restrict__ y)
{
    int lane16 = threadIdx.x & 15;
    int ch = threadIdx.x >> 4;
    int d = blockIdx.x * 8 + ch;
    float A = -__expf(A_log[d * DSTATE + lane16]);
    float Dd = Dvec[d];
    float h = 0.f;
    __shared__ float sB[32][16], sC[32][16], sdl[32][8], su[32][8], sre[32][8];
    for (int t0 = 0; t0 < LSEQ; t0 += 32) {
        __syncthreads();
        for (int i = threadIdx.x; i < 512; i += 128) {
            int tt = i >> 4, n = i & 15;
            const float* xb = xdbl + (size_t)(t0 + tt) * XDBL;
            sB[tt][n] = xb[DTRANK + n];
            sC[tt][n] = xb[DTRANK + DSTATE + n];
        }
        for (int i = threadIdx.x; i < 256; i += 128) {
            int tt = i >> 3, c = i & 7;
            int dd = blockIdx.x * 8 + c;
            size_t off = (size_t)(t0 + tt) * DINNER + dd;
            sdl[tt][c] = delta[off];
            su[tt][c]  = u[off];
            sre[tt][c] = xr[(size_t)(t0 + tt) * (2 * DINNER) + DINNER + dd];
        }
        __syncthreads();
        for (int tt = 0; tt < 32; tt++) {
            float dl = sdl[tt][ch];
            float uu = su[tt][ch];
            float dA = __expf(dl * A);
            h = dA * h + dl * sB[tt][lane16] * uu;
            float p = h * sC[tt][lane16];
            #pragma unroll
            for (int o = 8; o; o >>= 1) p += __shfl_xor_sync(0xffffffffu, p, o, 16);
            if (lane16 == 0) {
                float yv = p + uu * Dd;
                float r = sre[tt][ch];
                yv *= r / (1.f + __expf(-r));
                y[(size_t)(t0 + tt) * DINNER + d] = yv;
            }
        }
    }
}

// ---------------- gating: GEMV + softmax + top-2 ----------------
__global__ void gate_topk(const float* __restrict__ X, const float* __restrict__ gw,
                          int* __restrict__ te, float* __restrict__ tv)
{
    __shared__ float sg[NEXP * DMODEL];
    for (int i = threadIdx.x; i < NEXP * DMODEL; i += 128) sg[i] = gw[i];
    __syncthreads();
    int warp = threadIdx.x >> 5, lane = threadIdx.x & 31;
    int t = blockIdx.x * 4 + warp;
    const float* xp = X + (size_t)t * DMODEL;
    float acc[NEXP] = {};
    for (int k = lane; k < DMODEL; k += 32) {
        float xv = xp[k];
        #pragma unroll
        for (int e = 0; e < NEXP; e++) acc[e] += xv * sg[e * DMODEL + k];
    }
    #pragma unroll
    for (int e = 0; e < NEXP; e++)
        #pragma unroll
        for (int o = 16; o; o >>= 1) acc[e] += __shfl_xor_sync(0xffffffffu, acc[e], o);
    if (lane == 0) {
        float m = acc[0];
        #pragma unroll
        for (int e = 1; e < NEXP; e++) m = fmaxf(m, acc[e]);
        float g[NEXP];
        #pragma unroll
        for (int e = 0; e < NEXP; e++) g[e] = __expf(acc[e] - m);
        int i0 = 0;
        #pragma unroll
        for (int e = 1; e < NEXP; e++) if (g[e] > g[i0]) i0 = e;
        int i1 = (i0 == 0) ? 1 : 0;
        #pragma unroll
        for (int e = 0; e < NEXP; e++) if (e != i0 && g[e] > g[i1]) i1 = e;
        float inv = 1.f / (g[i0] + g[i1]);
        te[t * 2] = i0; te[t * 2 + 1] = i1;
        tv[t * 2] = g[i0] * inv; tv[t * 2 + 1] = g[i1] * inv;
    }
}

// ---------------- routing ----------------
__global__ void route_zero(int* cnt, int* cur)
{
    if (threadIdx.x < NEXP) { cnt[threadIdx.x] = 0; cur[threadIdx.x] = 0; }
}
__global__ void route_count(const int* __restrict__ te, int* cnt)
{
    int t = blockIdx.x * 256 + threadIdx.x;
    atomicAdd(&cnt[te[t * 2]], 1);
    atomicAdd(&cnt[te[t * 2 + 1]], 1);
}
__global__ void route_offsets(const int* __restrict__ cnt, int* off)
{
    int s = 0;
    for (int e = 0; e < NEXP; e++) { off[e] = s; s += cnt[e]; }
    off[NEXP] = s;
}
__global__ void route_scatter(const int* __restrict__ te, const float* __restrict__ tv,
                              const int* __restrict__ off, int* cur,
                              int* ptok, float* pw, int* tok_pair)
{
    int t = blockIdx.x * 256 + threadIdx.x;
    #pragma unroll
    for (int k = 0; k < 2; k++) {
        int e = te[t * 2 + k];
        int pos = atomicAdd(&cur[e], 1);
        int p = off[e] + pos;
        ptok[p] = t;
        pw[p] = tv[t * 2 + k];
        tok_pair[t * 2 + k] = p;
    }
}

// ---------------- final combine ----------------
__global__ void moe_combine(const float* __restrict__ x, const float* __restrict__ y2,
                            const int* __restrict__ tok_pair, const float* __restrict__ pw,
                            float* __restrict__ out)
{
    int i = blockIdx.x * 256 + threadIdx.x;
    int t = i >> 10, n = i & (DMODEL - 1);
    int p0 = tok_pair[t * 2], p1 = tok_pair[t * 2 + 1];
    out[i] = x[i] + pw[p0] * y2[(size_t)p0 * DMODEL + n]
                  + pw[p1] * y2[(size_t)p1 * DMODEL + n];
}

// ---------------- launch ----------------
extern "C" void kernel_launch(void* const* d_in, const int* in_sizes, int n_in,
                              void* d_out, int out_size)
{
    (void)in_sizes; (void)n_in; (void)out_size;
    const float* x          = (const float*)d_in[0];
    const float* in_proj_w  = (const float*)d_in[1];
    const float* conv_w     = (const float*)d_in[2];
    const float* conv_b     = (const float*)d_in[3];
    const float* x_proj_w   = (const float*)d_in[4];
    const float* dt_proj_w  = (const float*)d_in[5];
    const float* dt_proj_b  = (const float*)d_in[6];
    const float* A_log      = (const float*)d_in[7];
    const float* Dvec       = (const float*)d_in[8];
    const float* out_proj_w = (const float*)d_in[9];
    const float* gate_w     = (const float*)d_in[10];
    const float* w1         = (const float*)d_in[11];
    const float* w2         = (const float*)d_in[12];
    float* out = (float*)d_out;

    float *p_xn, *p_xr, *p_u, *p_xdbl, *p_xp, *p_delta, *p_y, *p_xm2, *p_xm2n, *p_tv, *p_pw, *p_h, *p_y2;
    int *p_te, *p_cnt, *p_cur, *p_off, *p_ptok, *p_tp;
    cudaGetSymbolAddress((void**)&p_xn, g_xn);
    cudaGetSymbolAddress((void**)&p_xr, g_xr);
    cudaGetSymbolAddress((void**)&p_u, g_u);
    cudaGetSymbolAddress((void**)&p_xdbl, g_xdbl);
    cudaGetSymbolAddress((void**)&p_xp, g_xp);
    cudaGetSymbolAddress((void**)&p_delta, g_delta);
    cudaGetSymbolAddress((void**)&p_y, g_y);
    cudaGetSymbolAddress((void**)&p_xm2, g_xm2);
    cudaGetSymbolAddress((void**)&p_xm2n, g_xm2n);
    cudaGetSymbolAddress((void**)&p_te, g_top_e);
    cudaGetSymbolAddress((void**)&p_tv, g_top_v);
    cudaGetSymbolAddress((void**)&p_cnt, g_cnt);
    cudaGetSymbolAddress((void**)&p_cur, g_cur);
    cudaGetSymbolAddress((void**)&p_off, g_off);
    cudaGetSymbolAddress((void**)&p_ptok, g_ptok);
    cudaGetSymbolAddress((void**)&p_pw, g_pw);
    cudaGetSymbolAddress((void**)&p_tp, g_tok_pair);
    cudaGetSymbolAddress((void**)&p_h, g_h);
    cudaGetSymbolAddress((void**)&p_y2, g_y2);

    // 1. xn = rmsnorm(x)
    rmsnorm_kernel<<<LSEQ, 256>>>(x, p_xn);
    // 2. xr = xn @ in_proj_w^T   (2048 x 4096, K=1024) [bf16 tensor]
    bmma_gemm<0, 0><<<dim3(16, 32), 256>>>(p_xn, DMODEL, in_proj_w, DMODEL,
                                           p_xr, 2 * DINNER, LSEQ, 2 * DINNER,
                                           nullptr, nullptr, 0, nullptr, nullptr);
    // 3. u = silu(causal_conv(xm) + b)
    conv_silu<<<(LSEQ * DINNER) / 256, 256>>>(p_xr, conv_w, conv_b, p_u);
    // 4. x_dbl = u @ x_proj_w^T  (2048 x 96, K=2048) [split-K=4 SIMT, exact]
    gemm_sk<<<dim3(32, 2, 4), 256>>>(p_u, DINNER, x_proj_w, DINNER,
                                     p_xp, XDBL, LSEQ, XDBL, DINNER / 4);
    reduce4<<<(LSEQ * XDBL + 255) / 256, 256>>>(p_xp, p_xdbl, LSEQ * XDBL);
    // 5. delta = softplus(dt @ dt_proj_w^T + b)  (2048 x 2048, K=64) [bf16 tensor]
    bmma_gemm<3, 0><<<dim3(16, 16), 256>>>(p_xdbl, XDBL, dt_proj_w, DTRANK,
                                           p_delta, DINNER, LSEQ, DINNER,
                                           dt_proj_b, nullptr, 0, nullptr, nullptr);
    // 6. selective scan
    scan_kernel<<<DINNER / 8, 128>>>(p_delta, p_u, p_xdbl, A_log, Dvec, p_xr, p_y);
    // 7. xm2 = y @ out_proj_w^T + xn  (2048 x 1024, K=2048) [bf16 tensor]
    bmma_gemm<2, 0><<<dim3(16, 8), 256>>>(p_y, DINNER, out_proj_w, DINNER,
                                          p_xm2, DMODEL, LSEQ, DMODEL,
                                          nullptr, p_xn, DMODEL, nullptr, nullptr);
    // 8. xm2n = rmsnorm(xm2)
    rmsnorm_kernel<<<LSEQ, 256>>>(p_xm2, p_xm2n);
    // 9. gating + top-2
    gate_topk<<<LSEQ / 4, 128>>>(p_xm2n, gate_w, p_te, p_tv);
    // 10. routing
    route_zero<<<1, 32>>>(p_cnt, p_cur);
    route_count<<<LSEQ / 256, 256>>>(p_te, p_cnt);
    route_offsets<<<1, 1>>>(p_cnt, p_off);
    route_scatter<<<LSEQ / 256, 256>>>(p_te, p_tv, p_off, p_cur, p_ptok, p_pw, p_tp);
    // 11. expert GEMMs [bf16 tensor]
    bmma_gemm<1, 1><<<dim3(32, 32, NEXP), 256>>>(p_xm2n, DMODEL, w1, DMODEL,
                                                 p_h, HIDDEN, 0, HIDDEN,
                                                 nullptr, nullptr, 0, p_off, p_ptok);
    bmma_gemm<0, 2><<<dim3(32, 8, NEXP), 256>>>(p_h, HIDDEN, w2, HIDDEN,
                                                p_y2, DMODEL, 0, DMODEL,
                                                nullptr, nullptr, 0, p_off, nullptr);
    moe_combine<<<(LSEQ * DMODEL) / 256, 256>>>(x, p_y2, p_tp, p_pw, out);
}